// round 1
// baseline (speedup 1.0000x reference)
#include <cuda_runtime.h>

// Problem constants
#define BB   8      // batch
#define CC   256    // channels
#define SS   1024   // sequence (32*32)
#define NH   8      // heads
#define DK   256    // head dim
#define HD   2048   // NH*DK
#define QKVN 6144   // NH*DK*3

#define BM 128
#define BN 128
#define BKK 8

// Scratch (device globals: allocation-free per harness rules)
static __device__ float g_q[BB * NH * SS * DK];        // 64 MB  [b][h][s][d]
static __device__ float g_k[BB * NH * SS * DK];        // 64 MB
static __device__ float g_v[BB * NH * SS * DK];        // 64 MB
static __device__ float g_scores[(size_t)BB * NH * SS * SS]; // 256 MB [b][h][i][j]
static __device__ float g_attnout[BB * SS * HD];       // 64 MB  [b][s][h*DK+d]

// ---------------------------------------------------------------------------
// 8x8-per-thread microkernel over one [8][128]x[8][128] smem tile pair
// ---------------------------------------------------------------------------
__device__ __forceinline__ void mm_tile(const float (&As)[BKK][BM],
                                        const float (&Bs)[BKK][BN],
                                        float (&acc)[8][8], int ty, int tx) {
#pragma unroll
    for (int k = 0; k < BKK; ++k) {
        float4 a0 = *reinterpret_cast<const float4*>(&As[k][ty * 8 + 0]);
        float4 a1 = *reinterpret_cast<const float4*>(&As[k][ty * 8 + 4]);
        float4 b0 = *reinterpret_cast<const float4*>(&Bs[k][tx * 8 + 0]);
        float4 b1 = *reinterpret_cast<const float4*>(&Bs[k][tx * 8 + 4]);
        float a[8] = {a0.x, a0.y, a0.z, a0.w, a1.x, a1.y, a1.z, a1.w};
        float b[8] = {b0.x, b0.y, b0.z, b0.w, b1.x, b1.y, b1.z, b1.w};
#pragma unroll
        for (int i = 0; i < 8; ++i)
#pragma unroll
            for (int j = 0; j < 8; ++j)
                acc[i][j] = fmaf(a[i], b[j], acc[i][j]);
    }
}

// ---------------------------------------------------------------------------
// Kernel 1: qkv = xt @ Wp + bp, scattered to g_q/g_k/g_v
//   A[m,k] = x[b, k, s]  (m = b*SS + s)  -> "direct" load (k rows contiguous in m)
//   B = Wp [256, 6144] row-major        -> direct
// ---------------------------------------------------------------------------
__global__ __launch_bounds__(256) void qkv_gemm(const float* __restrict__ x,
                                                const float* __restrict__ Wp,
                                                const float* __restrict__ bp) {
    __shared__ float As[BKK][BM];
    __shared__ float Bs[BKK][BN];
    int tid = threadIdx.x;
    int n0 = blockIdx.x * BN;
    int mg0 = blockIdx.y * BM;
    int b = mg0 >> 10;
    int s0 = mg0 & 1023;
    int ty = tid >> 4, tx = tid & 15;
    int lk = tid >> 5, lc = (tid & 31) << 2;
    float acc[8][8] = {};

    for (int kt = 0; kt < CC; kt += BKK) {
        float4 av = *reinterpret_cast<const float4*>(
            x + ((size_t)(b * CC + kt + lk) << 10) + s0 + lc);
        *reinterpret_cast<float4*>(&As[lk][lc]) = av;
        float4 bv = *reinterpret_cast<const float4*>(
            Wp + (size_t)(kt + lk) * QKVN + n0 + lc);
        *reinterpret_cast<float4*>(&Bs[lk][lc]) = bv;
        __syncthreads();
        mm_tile(As, Bs, acc, ty, tx);
        __syncthreads();
    }

#pragma unroll
    for (int i = 0; i < 8; ++i) {
        int s = s0 + ty * 8 + i;
#pragma unroll
        for (int j = 0; j < 8; ++j) {
            int n = n0 + tx * 8 + j;
            float val = acc[i][j] + bp[n];
            int h = n / 768;
            int loc = n - h * 768;
            float* dst = (loc < 256) ? g_q : (loc < 512) ? g_k : g_v;
            int d = loc & 255;
            dst[(((size_t)(b * NH + h) << 10) + s) * DK + d] = val;
        }
    }
}

// ---------------------------------------------------------------------------
// Kernel 2: scores[b,h,i,j] = SCALE * sum_d Q[i,d] K[j,d]   per (b,h)
//   Both operands row-major [S, DK] -> transpose loads into smem
// ---------------------------------------------------------------------------
__global__ __launch_bounds__(256) void qk_gemm() {
    __shared__ float As[BKK][BM];
    __shared__ float Bs[BKK][BN];
    int tid = threadIdx.x;
    int bh = blockIdx.z;
    const float* Q = g_q + ((size_t)bh << 18);
    const float* Kp = g_k + ((size_t)bh << 18);
    int m0 = blockIdx.y * BM, j0 = blockIdx.x * BN;
    int ty = tid >> 4, tx = tid & 15;
    int lm = tid >> 1, lk = (tid & 1) << 2;
    float acc[8][8] = {};

    for (int kt = 0; kt < DK; kt += BKK) {
        float4 av = *reinterpret_cast<const float4*>(Q + (size_t)(m0 + lm) * DK + kt + lk);
        As[lk + 0][lm] = av.x; As[lk + 1][lm] = av.y;
        As[lk + 2][lm] = av.z; As[lk + 3][lm] = av.w;
        float4 bv = *reinterpret_cast<const float4*>(Kp + (size_t)(j0 + lm) * DK + kt + lk);
        Bs[lk + 0][lm] = bv.x; Bs[lk + 1][lm] = bv.y;
        Bs[lk + 2][lm] = bv.z; Bs[lk + 3][lm] = bv.w;
        __syncthreads();
        mm_tile(As, Bs, acc, ty, tx);
        __syncthreads();
    }

    size_t base = ((size_t)bh << 20);
#pragma unroll
    for (int i = 0; i < 8; ++i) {
        size_t rowoff = base + ((size_t)(m0 + ty * 8 + i) << 10) + j0 + tx * 8;
        float4* dst = reinterpret_cast<float4*>(&g_scores[rowoff]);
        dst[0] = make_float4(acc[i][0] * 0.0625f, acc[i][1] * 0.0625f,
                             acc[i][2] * 0.0625f, acc[i][3] * 0.0625f);
        dst[1] = make_float4(acc[i][4] * 0.0625f, acc[i][5] * 0.0625f,
                             acc[i][6] * 0.0625f, acc[i][7] * 0.0625f);
    }
}

// ---------------------------------------------------------------------------
// Kernel 3: row softmax over j (1024 per row), in place
// ---------------------------------------------------------------------------
__global__ __launch_bounds__(256) void softmax_kernel() {
    size_t row = blockIdx.x;
    float* p = g_scores + (row << 10);
    int tid = threadIdx.x;
    float4 v = reinterpret_cast<float4*>(p)[tid];

    float m = fmaxf(fmaxf(v.x, v.y), fmaxf(v.z, v.w));
#pragma unroll
    for (int o = 16; o; o >>= 1) m = fmaxf(m, __shfl_xor_sync(0xffffffffu, m, o));
    __shared__ float redm[8];
    __shared__ float reds[8];
    if ((tid & 31) == 0) redm[tid >> 5] = m;
    __syncthreads();
    m = redm[0];
#pragma unroll
    for (int w = 1; w < 8; ++w) m = fmaxf(m, redm[w]);

    v.x = __expf(v.x - m);
    v.y = __expf(v.y - m);
    v.z = __expf(v.z - m);
    v.w = __expf(v.w - m);
    float s = v.x + v.y + v.z + v.w;
#pragma unroll
    for (int o = 16; o; o >>= 1) s += __shfl_xor_sync(0xffffffffu, s, o);
    if ((tid & 31) == 0) reds[tid >> 5] = s;
    __syncthreads();
    s = reds[0];
#pragma unroll
    for (int w = 1; w < 8; ++w) s += reds[w];

    float inv = 1.0f / s;
    v.x *= inv; v.y *= inv; v.z *= inv; v.w *= inv;
    reinterpret_cast<float4*>(p)[tid] = v;
}

// ---------------------------------------------------------------------------
// Kernel 4: attnout[b,s,h*DK+n] = sum_j P[i,j] V[j,n]   per (b,h)
//   A = P [S,S] row-major -> transpose load; B = V [S,DK] -> direct load
// ---------------------------------------------------------------------------
__global__ __launch_bounds__(256) void pv_gemm() {
    __shared__ float As[BKK][BM];
    __shared__ float Bs[BKK][BN];
    int tid = threadIdx.x;
    int bh = blockIdx.z;
    const float* P = g_scores + ((size_t)bh << 20);
    const float* V = g_v + ((size_t)bh << 18);
    int m0 = blockIdx.y * BM, n0 = blockIdx.x * BN;
    int ty = tid >> 4, tx = tid & 15;
    int lm = tid >> 1, lk = (tid & 1) << 2;
    int lkd = tid >> 5, lcd = (tid & 31) << 2;
    float acc[8][8] = {};

    for (int kt = 0; kt < SS; kt += BKK) {
        float4 av = *reinterpret_cast<const float4*>(P + ((size_t)(m0 + lm) << 10) + kt + lk);
        As[lk + 0][lm] = av.x; As[lk + 1][lm] = av.y;
        As[lk + 2][lm] = av.z; As[lk + 3][lm] = av.w;
        float4 bv = *reinterpret_cast<const float4*>(V + (size_t)(kt + lkd) * DK + n0 + lcd);
        *reinterpret_cast<float4*>(&Bs[lkd][lcd]) = bv;
        __syncthreads();
        mm_tile(As, Bs, acc, ty, tx);
        __syncthreads();
    }

    int b = bh >> 3, h = bh & 7;
#pragma unroll
    for (int i = 0; i < 8; ++i) {
        int s = m0 + ty * 8 + i;
        size_t off = ((size_t)(b * SS + s)) * HD + h * DK + n0 + tx * 8;
        float4* dst = reinterpret_cast<float4*>(&g_attnout[off]);
        dst[0] = make_float4(acc[i][0], acc[i][1], acc[i][2], acc[i][3]);
        dst[1] = make_float4(acc[i][4], acc[i][5], acc[i][6], acc[i][7]);
    }
}

// ---------------------------------------------------------------------------
// Kernel 5: out[b,n,s] = attnout[b,s,:] @ Wo[:,n] + bo[n] + x[b,n,s]
//   A = attnout [8192,2048] row-major -> transpose; B = Wo [2048,256] direct
// ---------------------------------------------------------------------------
__global__ __launch_bounds__(256) void proj_gemm(const float* __restrict__ x,
                                                 const float* __restrict__ Wo,
                                                 const float* __restrict__ bo,
                                                 float* __restrict__ out) {
    __shared__ float As[BKK][BM];
    __shared__ float Bs[BKK][BN];
    int tid = threadIdx.x;
    int m0 = blockIdx.y * BM, n0 = blockIdx.x * BN;
    int ty = tid >> 4, tx = tid & 15;
    int lm = tid >> 1, lk = (tid & 1) << 2;
    int lkd = tid >> 5, lcd = (tid & 31) << 2;
    float acc[8][8] = {};

    for (int kt = 0; kt < HD; kt += BKK) {
        float4 av = *reinterpret_cast<const float4*>(
            g_attnout + (size_t)(m0 + lm) * HD + kt + lk);
        As[lk + 0][lm] = av.x; As[lk + 1][lm] = av.y;
        As[lk + 2][lm] = av.z; As[lk + 3][lm] = av.w;
        float4 bv = *reinterpret_cast<const float4*>(
            Wo + (size_t)(kt + lkd) * CC + n0 + lcd);
        *reinterpret_cast<float4*>(&Bs[lkd][lcd]) = bv;
        __syncthreads();
        mm_tile(As, Bs, acc, ty, tx);
        __syncthreads();
    }

#pragma unroll
    for (int i = 0; i < 8; ++i) {
        int mg = m0 + ty * 8 + i;
        int b = mg >> 10;
        int s = mg & 1023;
#pragma unroll
        for (int j = 0; j < 8; ++j) {
            int n = n0 + tx * 8 + j;
            size_t idx = ((size_t)(b * CC + n) << 10) + s;
            out[idx] = acc[i][j] + bo[n] + x[idx];
        }
    }
}

// ---------------------------------------------------------------------------
extern "C" void kernel_launch(void* const* d_in, const int* in_sizes, int n_in,
                              void* d_out, int out_size) {
    const float* x  = (const float*)d_in[0];
    const float* Wp = (const float*)d_in[1];
    const float* bp = (const float*)d_in[2];
    const float* Wo = (const float*)d_in[3];
    const float* bo = (const float*)d_in[4];
    float* out = (float*)d_out;

    qkv_gemm<<<dim3(QKVN / BN, (BB * SS) / BM), 256>>>(x, Wp, bp);
    qk_gemm<<<dim3(SS / BN, SS / BM, BB * NH), 256>>>();
    softmax_kernel<<<BB * NH * SS, 256>>>();
    pv_gemm<<<dim3(DK / BN, SS / BM, BB * NH), 256>>>();
    proj_gemm<<<dim3(CC / BN, (BB * SS) / BM), 256>>>(x, Wo, bo, out);
}

// round 3
// speedup vs baseline: 3.4683x; 3.4683x over previous
#include <cuda_runtime.h>
#include <cuda_bf16.h>
#include <cstdint>
#include <cstddef>

// ---------------------------------------------------------------------------
// Problem constants
// ---------------------------------------------------------------------------
#define BB 8
#define CC 256
#define SS 1024
#define NH 8
#define DK 256
#define HD 2048
#define QKVN 6144

#define BM 128
#define BN 128
#define BKF 32          // fp32 K per block
#define PAD 40          // bf16 elements per smem row (80B, conflict-free)

// ---------------------------------------------------------------------------
// Device scratch (allocation-free per harness rules)
// ---------------------------------------------------------------------------
__device__ float g_xt[BB * SS * CC];                  // [b*S+s][c]
__device__ float g_WpT[QKVN * CC];                    // [n][k]
__device__ float g_WoT[CC * HD];                      // [n][k]
__device__ float g_q[BB * NH * SS * DK];              // [bh][s][d]
__device__ float g_k[BB * NH * SS * DK];
__device__ float g_v[BB * NH * SS * DK];
__device__ float g_vt[BB * NH * DK * SS];             // [bh][d][s]
__device__ float g_scores[(size_t)BB * NH * SS * SS]; // [bh][i][j]
__device__ float g_attnout[BB * SS * HD];             // [b*S+s][h*DK+d]

// ---------------------------------------------------------------------------
// PTX helpers (portable: sm_75+/sm_80+, no arch-specific 'a' features)
// ---------------------------------------------------------------------------
__device__ __forceinline__ uint32_t smem_u32(const void* p) {
    uint32_t a;
    asm("{ .reg .u64 t; cvta.to.shared.u64 t, %1; cvt.u32.u64 %0, t; }"
        : "=r"(a) : "l"(p));
    return a;
}

__device__ __forceinline__ void ldsm4(uint32_t* r, uint32_t addr) {
    asm volatile("ldmatrix.sync.aligned.m8n8.x4.shared.b16 {%0,%1,%2,%3}, [%4];"
                 : "=r"(r[0]), "=r"(r[1]), "=r"(r[2]), "=r"(r[3]) : "r"(addr));
}

__device__ __forceinline__ void mma16816(float* d, const uint32_t* a,
                                         uint32_t b0, uint32_t b1) {
    asm volatile(
        "mma.sync.aligned.m16n8k16.row.col.f32.bf16.bf16.f32 "
        "{%0,%1,%2,%3}, {%4,%5,%6,%7}, {%8,%9}, {%0,%1,%2,%3};"
        : "+f"(d[0]), "+f"(d[1]), "+f"(d[2]), "+f"(d[3])
        : "r"(a[0]), "r"(a[1]), "r"(a[2]), "r"(a[3]), "r"(b0), "r"(b1));
}

// ---------------------------------------------------------------------------
// Generic batched transpose: in [Z][R][C] -> out [Z][C][R]
// ---------------------------------------------------------------------------
__global__ __launch_bounds__(256) void txp(const float* __restrict__ in,
                                           float* __restrict__ out, int R, int C) {
    __shared__ float t[32][33];
    int z = blockIdx.z;
    const float* I = in + (size_t)z * R * C;
    float* O = out + (size_t)z * R * C;
    int c0 = blockIdx.x * 32, r0 = blockIdx.y * 32;
    int x = threadIdx.x, y = threadIdx.y;
#pragma unroll
    for (int i = 0; i < 32; i += 8)
        t[y + i][x] = I[(size_t)(r0 + y + i) * C + c0 + x];
    __syncthreads();
#pragma unroll
    for (int i = 0; i < 32; i += 8)
        O[(size_t)(c0 + y + i) * R + r0 + x] = t[x][y + i];
}

// ---------------------------------------------------------------------------
// bf16x3 split-precision GEMM: C[128,128] tile = A[128,K] * B[128,K]^T
// MODE 0: QKV (bias + scatter to g_q/g_k/g_v)
// MODE 1: QK^T (scale, store C)
// MODE 2: PV (store into g_attnout)
// MODE 3: out-proj (bias + residual + transposed store via smem)
// ---------------------------------------------------------------------------
template <int MODE>
__global__ __launch_bounds__(256) void gemm_bf16x3(
    const float* __restrict__ A, const float* __restrict__ B, float* __restrict__ C,
    int K, int ldA, int ldB, int ldC, size_t Az, size_t Bz, size_t Cz,
    const float* __restrict__ bias, const float* __restrict__ resid, float scale) {
    // smem tiles: [0]=A_hi [1]=A_lo [2]=B_hi [3]=B_lo, each 128 rows x PAD bf16
    __shared__ __align__(16) __nv_bfloat16 smt[4][128 * PAD];

    const int tid = threadIdx.x;
    const int wid = tid >> 5;
    const int lane = tid & 31;
    const int wr = wid >> 1;   // warp row 0..3 (32 rows each)
    const int wc = wid & 1;    // warp col 0..1 (64 cols each)

    const int z = blockIdx.z;
    const int m0 = blockIdx.y * BM;
    const int n0 = blockIdx.x * BN;
    const float* Ab = A + Az * z + (size_t)m0 * ldA;
    const float* Bb = B + Bz * z + (size_t)n0 * ldB;
    const int NKB = K / BKF;

    const uint32_t sA_hi = smem_u32(&smt[0][0]);
    const uint32_t sA_lo = smem_u32(&smt[1][0]);
    const uint32_t sB_hi = smem_u32(&smt[2][0]);
    const uint32_t sB_lo = smem_u32(&smt[3][0]);

    // ldmatrix per-lane byte offsets (k-offset added at use site)
    const int lr = lane & 15, lhf = lane >> 4;
    uint32_t aoff[2], boff[4];
#pragma unroll
    for (int im = 0; im < 2; ++im)
        aoff[im] = ((wr * 32 + im * 16 + lr) * PAD + lhf * 8) * 2;
#pragma unroll
    for (int jn = 0; jn < 4; ++jn)
        boff[jn] = ((wc * 64 + jn * 16 + lr) * PAD + lhf * 8) * 2;

    // global loader indices: each thread does 4 float4 per matrix
    const int gr = tid >> 3;        // base row 0..31
    const int gc = tid & 7;         // float4 col 0..7 (elems gc*4)

    float4 ra[4], rb[4];
    auto ldg_blk = [&](int kb) {
#pragma unroll
        for (int i = 0; i < 4; ++i) {
            ra[i] = *(const float4*)(Ab + (size_t)(gr + 32 * i) * ldA + kb * BKF + gc * 4);
            rb[i] = *(const float4*)(Bb + (size_t)(gr + 32 * i) * ldB + kb * BKF + gc * 4);
        }
    };
    auto sts_blk = [&]() {
#pragma unroll
        for (int i = 0; i < 4; ++i) {
            int base = (gr + 32 * i) * PAD + gc * 4;
            float4 v = ra[i];
            __nv_bfloat162 h01, h23, l01, l23;
            h01.x = __float2bfloat16(v.x); h01.y = __float2bfloat16(v.y);
            h23.x = __float2bfloat16(v.z); h23.y = __float2bfloat16(v.w);
            l01.x = __float2bfloat16(v.x - __bfloat162float(h01.x));
            l01.y = __float2bfloat16(v.y - __bfloat162float(h01.y));
            l23.x = __float2bfloat16(v.z - __bfloat162float(h23.x));
            l23.y = __float2bfloat16(v.w - __bfloat162float(h23.y));
            *(__nv_bfloat162*)(&smt[0][base]) = h01;
            *(__nv_bfloat162*)(&smt[0][base + 2]) = h23;
            *(__nv_bfloat162*)(&smt[1][base]) = l01;
            *(__nv_bfloat162*)(&smt[1][base + 2]) = l23;
            v = rb[i];
            h01.x = __float2bfloat16(v.x); h01.y = __float2bfloat16(v.y);
            h23.x = __float2bfloat16(v.z); h23.y = __float2bfloat16(v.w);
            l01.x = __float2bfloat16(v.x - __bfloat162float(h01.x));
            l01.y = __float2bfloat16(v.y - __bfloat162float(h01.y));
            l23.x = __float2bfloat16(v.z - __bfloat162float(h23.x));
            l23.y = __float2bfloat16(v.w - __bfloat162float(h23.y));
            *(__nv_bfloat162*)(&smt[2][base]) = h01;
            *(__nv_bfloat162*)(&smt[2][base + 2]) = h23;
            *(__nv_bfloat162*)(&smt[3][base]) = l01;
            *(__nv_bfloat162*)(&smt[3][base + 2]) = l23;
        }
    };

    float acc[2][8][4] = {};

    ldg_blk(0);
    sts_blk();
    __syncthreads();

    for (int kb = 0; kb < NKB; ++kb) {
        if (kb + 1 < NKB) ldg_blk(kb + 1);

#pragma unroll
        for (int ks = 0; ks < 32; ks += 16) {
            const uint32_t kso = ks * 2;
            uint32_t ah[2][4], axl[2][4], bbf[4][4];
            ldsm4(ah[0], sA_hi + aoff[0] + kso);
            ldsm4(ah[1], sA_hi + aoff[1] + kso);
#pragma unroll
            for (int jn = 0; jn < 4; ++jn) ldsm4(bbf[jn], sB_hi + boff[jn] + kso);
            // hi*hi
#pragma unroll
            for (int im = 0; im < 2; ++im)
#pragma unroll
                for (int jn = 0; jn < 4; ++jn) {
                    mma16816(acc[im][jn * 2], ah[im], bbf[jn][0], bbf[jn][2]);
                    mma16816(acc[im][jn * 2 + 1], ah[im], bbf[jn][1], bbf[jn][3]);
                }
            // lo*hi
            ldsm4(axl[0], sA_lo + aoff[0] + kso);
            ldsm4(axl[1], sA_lo + aoff[1] + kso);
#pragma unroll
            for (int im = 0; im < 2; ++im)
#pragma unroll
                for (int jn = 0; jn < 4; ++jn) {
                    mma16816(acc[im][jn * 2], axl[im], bbf[jn][0], bbf[jn][2]);
                    mma16816(acc[im][jn * 2 + 1], axl[im], bbf[jn][1], bbf[jn][3]);
                }
            // hi*lo (reuse bbf for B_lo)
#pragma unroll
            for (int jn = 0; jn < 4; ++jn) ldsm4(bbf[jn], sB_lo + boff[jn] + kso);
#pragma unroll
            for (int im = 0; im < 2; ++im)
#pragma unroll
                for (int jn = 0; jn < 4; ++jn) {
                    mma16816(acc[im][jn * 2], ah[im], bbf[jn][0], bbf[jn][2]);
                    mma16816(acc[im][jn * 2 + 1], ah[im], bbf[jn][1], bbf[jn][3]);
                }
        }
        __syncthreads();
        if (kb + 1 < NKB) {
            sts_blk();
            __syncthreads();
        }
    }

    // ---- epilogue ----
    const int r0l = lane >> 2;
    const int c0l = (lane & 3) * 2;

    if (MODE == 0) {
        const int hB = n0 / 768;
        const int loc0 = n0 % 768;
        const int seg = loc0 >> 8;
        const int d0 = loc0 & 255;
        float* dstb = (seg == 0) ? g_q : (seg == 1) ? g_k : g_v;
#pragma unroll
        for (int im = 0; im < 2; ++im)
#pragma unroll
            for (int jn = 0; jn < 8; ++jn)
#pragma unroll
                for (int p = 0; p < 2; ++p) {
                    int m = m0 + wr * 32 + im * 16 + r0l + p * 8;
                    int nb = wc * 64 + jn * 8 + c0l;
                    int b = m >> 10, s2 = m & 1023;
                    size_t row = ((size_t)(b * NH + hB) * SS + s2) * DK;
                    float2 o;
                    o.x = acc[im][jn][p * 2] + bias[n0 + nb];
                    o.y = acc[im][jn][p * 2 + 1] + bias[n0 + nb + 1];
                    *(float2*)(dstb + row + d0 + nb) = o;
                }
    } else if (MODE == 1) {
        float* Cb = C + Cz * z;
#pragma unroll
        for (int im = 0; im < 2; ++im)
#pragma unroll
            for (int jn = 0; jn < 8; ++jn)
#pragma unroll
                for (int p = 0; p < 2; ++p) {
                    int m = m0 + wr * 32 + im * 16 + r0l + p * 8;
                    int nb = wc * 64 + jn * 8 + c0l;
                    float2 o;
                    o.x = acc[im][jn][p * 2] * scale;
                    o.y = acc[im][jn][p * 2 + 1] * scale;
                    *(float2*)(Cb + (size_t)m * ldC + n0 + nb) = o;
                }
    } else if (MODE == 2) {
        int b = z >> 3, h = z & 7;
        float* dst = g_attnout + (size_t)b * SS * HD + h * DK;
#pragma unroll
        for (int im = 0; im < 2; ++im)
#pragma unroll
            for (int jn = 0; jn < 8; ++jn)
#pragma unroll
                for (int p = 0; p < 2; ++p) {
                    int m = m0 + wr * 32 + im * 16 + r0l + p * 8;
                    int nb = wc * 64 + jn * 8 + c0l;
                    float2 o;
                    o.x = acc[im][jn][p * 2];
                    o.y = acc[im][jn][p * 2 + 1];
                    *(float2*)(dst + (size_t)m * HD + n0 + nb) = o;
                }
    } else {  // MODE 3: smem transpose -> coalesced [B,C,S] store + bias + resid
        float* sc = (float*)(&smt[0][0]);  // 128 x 65 fp32 = 33.3 KB (fits 40 KB)
        const int bB = m0 >> 10;
        const int s0 = m0 & 1023;
#pragma unroll
        for (int pass = 0; pass < 2; ++pass) {
            __syncthreads();
            if (wc == pass) {
#pragma unroll
                for (int im = 0; im < 2; ++im)
#pragma unroll
                    for (int jn = 0; jn < 8; ++jn)
#pragma unroll
                        for (int p = 0; p < 2; ++p) {
                            int rloc = wr * 32 + im * 16 + r0l + p * 8;
                            int cloc = jn * 8 + c0l;
                            sc[rloc * 65 + cloc] = acc[im][jn][p * 2];
                            sc[rloc * 65 + cloc + 1] = acc[im][jn][p * 2 + 1];
                        }
            }
            __syncthreads();
            int nl = tid >> 2;              // 0..63
            int sblk = (tid & 3) * 32;      // 0,32,64,96
            int n = n0 + pass * 64 + nl;
            size_t obase = (((size_t)(bB * CC + n)) << 10) + s0 + sblk;
            float bn = bias[n];
#pragma unroll
            for (int j = 0; j < 32; j += 4) {
                float4 xr = *(const float4*)(resid + obase + j);
                float4 o;
                o.x = sc[(sblk + j + 0) * 65 + nl] + bn + xr.x;
                o.y = sc[(sblk + j + 1) * 65 + nl] + bn + xr.y;
                o.z = sc[(sblk + j + 2) * 65 + nl] + bn + xr.z;
                o.w = sc[(sblk + j + 3) * 65 + nl] + bn + xr.w;
                *(float4*)(C + obase + j) = o;
            }
        }
    }
}

// ---------------------------------------------------------------------------
// Row softmax over 1024 cols, in place
// ---------------------------------------------------------------------------
__global__ __launch_bounds__(256) void softmax_kernel() {
    size_t row = blockIdx.x;
    float* p = g_scores + (row << 10);
    int tid = threadIdx.x;
    float4 v = reinterpret_cast<float4*>(p)[tid];

    float m = fmaxf(fmaxf(v.x, v.y), fmaxf(v.z, v.w));
#pragma unroll
    for (int o = 16; o; o >>= 1) m = fmaxf(m, __shfl_xor_sync(0xffffffffu, m, o));
    __shared__ float redm[8], reds[8];
    if ((tid & 31) == 0) redm[tid >> 5] = m;
    __syncthreads();
    m = redm[0];
#pragma unroll
    for (int w = 1; w < 8; ++w) m = fmaxf(m, redm[w]);

    v.x = __expf(v.x - m); v.y = __expf(v.y - m);
    v.z = __expf(v.z - m); v.w = __expf(v.w - m);
    float s = v.x + v.y + v.z + v.w;
#pragma unroll
    for (int o = 16; o; o >>= 1) s += __shfl_xor_sync(0xffffffffu, s, o);
    if ((tid & 31) == 0) reds[tid >> 5] = s;
    __syncthreads();
    s = reds[0];
#pragma unroll
    for (int w = 1; w < 8; ++w) s += reds[w];

    float inv = 1.0f / s;
    v.x *= inv; v.y *= inv; v.z *= inv; v.w *= inv;
    reinterpret_cast<float4*>(p)[tid] = v;
}

// ---------------------------------------------------------------------------
extern "C" void kernel_launch(void* const* d_in, const int* in_sizes, int n_in,
                              void* d_out, int out_size) {
    const float* x  = (const float*)d_in[0];
    const float* Wp = (const float*)d_in[1];
    const float* bp = (const float*)d_in[2];
    const float* Wo = (const float*)d_in[3];
    const float* bo = (const float*)d_in[4];
    float* out = (float*)d_out;

    float *p_xt, *p_WpT, *p_WoT, *p_q, *p_k, *p_v, *p_vt, *p_sc, *p_ao;
    cudaGetSymbolAddress((void**)&p_xt, g_xt);
    cudaGetSymbolAddress((void**)&p_WpT, g_WpT);
    cudaGetSymbolAddress((void**)&p_WoT, g_WoT);
    cudaGetSymbolAddress((void**)&p_q, g_q);
    cudaGetSymbolAddress((void**)&p_k, g_k);
    cudaGetSymbolAddress((void**)&p_v, g_v);
    cudaGetSymbolAddress((void**)&p_vt, g_vt);
    cudaGetSymbolAddress((void**)&p_sc, g_scores);
    cudaGetSymbolAddress((void**)&p_ao, g_attnout);

    dim3 tb(32, 8);
    // Pre-transposes: x -> xt, Wp -> WpT, Wo -> WoT
    txp<<<dim3(SS / 32, CC / 32, BB), tb>>>(x, p_xt, CC, SS);
    txp<<<dim3(QKVN / 32, CC / 32, 1), tb>>>(Wp, p_WpT, CC, QKVN);
    txp<<<dim3(CC / 32, HD / 32, 1), tb>>>(Wo, p_WoT, HD, CC);

    // QKV projection: [8192,256] @ [6144,256]^T
    gemm_bf16x3<0><<<dim3(QKVN / BN, (BB * SS) / BM, 1), 256>>>(
        p_xt, p_WpT, nullptr, CC, CC, CC, 0, 0, 0, 0, bp, nullptr, 1.0f);

    // V -> V^T per head
    txp<<<dim3(DK / 32, SS / 32, BB * NH), tb>>>(p_v, p_vt, SS, DK);

    // Q K^T (scaled): per bh, [1024,256] @ [1024,256]^T
    gemm_bf16x3<1><<<dim3(SS / BN, SS / BM, BB * NH), 256>>>(
        p_q, p_k, p_sc, DK, DK, DK, SS,
        (size_t)SS * DK, (size_t)SS * DK, (size_t)SS * SS, nullptr, nullptr, 0.0625f);

    softmax_kernel<<<BB * NH * SS, 256>>>();

    // P V: per bh, [1024,1024] @ [256,1024]^T
    gemm_bf16x3<2><<<dim3(DK / BN, SS / BM, BB * NH), 256>>>(
        p_sc, p_vt, nullptr, SS, SS, SS, 0,
        (size_t)SS * SS, (size_t)DK * SS, 0, nullptr, nullptr, 1.0f);

    // Out projection + bias + residual: [8192,2048] @ [256,2048]^T
    gemm_bf16x3<3><<<dim3(CC / BN, (BB * SS) / BM, 1), 256>>>(
        p_ao, p_WoT, out, HD, HD, HD, 0, 0, 0, 0, bo, x, 1.0f);
}